// round 9
// baseline (speedup 1.0000x reference)
#include <cuda_runtime.h>

#define J    24
#define TPB  64

__global__ __launch_bounds__(TPB) void fk_kernel(
    const float* __restrict__ angles,   // [B, 24]
    const float* __restrict__ Torg,     // [24, 4, 4]
    const float* __restrict__ axes,     // [24, 3] unit axes
    float* __restrict__ out,            // [B, 75]
    int B)
{
    // Per-joint derived constants: {wx,wy,wz,_, bx,by,bz,_}
    __shared__ __align__(16) float kjc[J][8];
    // Full output staging: thread t owns s_out[t*75 .. t*75+74].
    // Stride 75 odd -> bank-conflict-free; flushed once with float4.
    __shared__ __align__(16) float s_out[TPB * 75];

    const int tid  = threadIdx.x;
    const int warp = tid >> 5;
    const int lane = tid & 31;

    // ---- Warp 0: shuffle-scan of cumulative fixed rotations ----
    // C_j = Q_0 ... Q_j ;  w_j = C_j u_j ;  b_j = C_{j-1} t_j.
    if (warp == 0) {
        float m[9];
        float ax = 0.f, ay = 0.f, az = 0.f;
        float ux = 0.f, uy = 0.f, uz = 0.f;
        m[0]=1.f; m[1]=0.f; m[2]=0.f;
        m[3]=0.f; m[4]=1.f; m[5]=0.f;
        m[6]=0.f; m[7]=0.f; m[8]=1.f;
        if (lane < J) {
            const float* t = Torg + lane * 16;
            m[0]=t[0]; m[1]=t[1]; m[2]=t[2];   ax=t[3];
            m[3]=t[4]; m[4]=t[5]; m[5]=t[6];   ay=t[7];
            m[6]=t[8]; m[7]=t[9]; m[8]=t[10];  az=t[11];
            ux = axes[lane*3+0]; uy = axes[lane*3+1]; uz = axes[lane*3+2];
        }
        #pragma unroll
        for (int d = 1; d < J; d <<= 1) {          // inclusive Kogge-Stone
            float L[9];
            #pragma unroll
            for (int k = 0; k < 9; ++k)
                L[k] = __shfl_up_sync(0xffffffffu, m[k], d);
            if (lane >= d) {
                float n[9];
                #pragma unroll
                for (int r = 0; r < 3; ++r)
                    #pragma unroll
                    for (int c = 0; c < 3; ++c)
                        n[r*3+c] = L[r*3+0]*m[0*3+c] + L[r*3+1]*m[1*3+c]
                                 + L[r*3+2]*m[2*3+c];
                #pragma unroll
                for (int k = 0; k < 9; ++k) m[k] = n[k];
            }
        }
        float E[9];                                 // exclusive prefix
        #pragma unroll
        for (int k = 0; k < 9; ++k)
            E[k] = __shfl_up_sync(0xffffffffu, m[k], 1);
        if (lane == 0) {
            E[0]=1.f; E[1]=0.f; E[2]=0.f;
            E[3]=0.f; E[4]=1.f; E[5]=0.f;
            E[6]=0.f; E[7]=0.f; E[8]=1.f;
        }
        if (lane < J) {
            kjc[lane][0] = m[0]*ux + m[1]*uy + m[2]*uz;   // w = C_j u
            kjc[lane][1] = m[3]*ux + m[4]*uy + m[5]*uz;
            kjc[lane][2] = m[6]*ux + m[7]*uy + m[8]*uz;
            kjc[lane][3] = 0.f;
            kjc[lane][4] = E[0]*ax + E[1]*ay + E[2]*az;   // b = C_{j-1} t
            kjc[lane][5] = E[3]*ax + E[4]*ay + E[5]*az;
            kjc[lane][6] = E[6]*ax + E[7]*ay + E[8]*az;
            kjc[lane][7] = 0.f;
        }
    }

    const int base = blockIdx.x * TPB;
    const int e = base + tid;
    const bool active = (e < B);

    // All 24 angles up front: 6 LDG.128 (row start b*96 B is 16B aligned).
    float a[J];
    if (active) {
        const float4* ap = reinterpret_cast<const float4*>(angles + (size_t)e * J);
        #pragma unroll
        for (int q = 0; q < J / 4; ++q) {
            float4 v = __ldg(ap + q);
            a[4*q+0] = v.x; a[4*q+1] = v.y; a[4*q+2] = v.z; a[4*q+3] = v.w;
        }
    }

    __syncthreads();   // kjc ready

    if (active) {
        // State: quaternion P (w,x,y,z) and position p.
        float Pw = 1.f, Px = 0.f, Py = 0.f, Pz = 0.f;
        float px = 0.f, py = 0.f, pz = 0.f;

        float* so = s_out + tid * 75;
        so[0] = 0.f; so[1] = 0.f; so[2] = 0.f;   // base_pos

        const float4* kc = reinterpret_cast<const float4*>(kjc);

        #pragma unroll
        for (int j = 0; j < J; ++j) {
            const float4 wv = kc[2*j];       // w_j
            const float4 bv = kc[2*j + 1];   // b_j

            // p += rot(P, b):  t = qv x b;  p += b + 2*Pw*t + 2*(qv x t)
            const float tx = Py*bv.z - Pz*bv.y;
            const float ty = Pz*bv.x - Px*bv.z;
            const float tz = Px*bv.y - Py*bv.x;
            const float w2 = Pw + Pw;
            const float ox = Py*tz - Pz*ty;
            const float oy = Pz*tx - Px*tz;
            const float oz = Px*ty - Py*tx;
            px += bv.x + w2*tx + 2.f*ox;
            py += bv.y + w2*ty + 2.f*oy;
            pz += bv.z + w2*tz + 2.f*oz;

            so[3 + 3*j + 0] = px;
            so[3 + 3*j + 1] = py;
            so[3 + 3*j + 2] = pz;

            // P <- P (x) (cos h, sin h * w)   [skip after last joint]
            if (j < J - 1) {
                float s, co;
                __sincosf(0.5f * a[j], &s, &co);
                const float qx = s*wv.x, qy = s*wv.y, qz = s*wv.z;
                const float nw = Pw*co - Px*qx - Py*qy - Pz*qz;
                const float nx = Pw*qx + Px*co + Py*qz - Pz*qy;
                const float ny = Pw*qy - Px*qz + Py*co + Pz*qx;
                const float nz = Pw*qz + Px*qy - Py*qx + Pz*co;
                Pw = nw; Px = nx; Py = ny; Pz = nz;
            }
        }
    }

    __syncthreads();   // s_out fully staged

    // Single fully-coalesced float4 flush of the [TPB, 75] slab.
    const int nvalid = min(TPB, B - base);
    float* gout = out + (size_t)base * 75;
    if (nvalid == TPB) {
        const float4* sv = reinterpret_cast<const float4*>(s_out);
        float4* gv = reinterpret_cast<float4*>(gout);
        #pragma unroll 5
        for (int i = tid; i < TPB * 75 / 4; i += TPB) gv[i] = sv[i];
    } else if (nvalid > 0) {
        const int cnt = nvalid * 75;
        for (int i = tid; i < cnt; i += TPB) gout[i] = s_out[i];
    }
}

extern "C" void kernel_launch(void* const* d_in, const int* in_sizes, int n_in,
                              void* d_out, int out_size) {
    const float* angles = (const float*)d_in[0];   // [B, 24]
    const float* Torg   = (const float*)d_in[1];   // [24, 4, 4]
    const float* axes   = (const float*)d_in[2];   // [24, 3]
    float* out = (float*)d_out;                    // [B, 75]

    const int B = in_sizes[0] / J;
    const int blocks = (B + TPB - 1) / TPB;
    fk_kernel<<<blocks, TPB>>>(angles, Torg, axes, out, B);
}